// round 15
// baseline (speedup 1.0000x reference)
#include <cuda_runtime.h>
#include <cuda_fp16.h>
#include <cstdint>

#define N_NODES 100000
#define N_EDGES 1600000
#define C 128          // IN_C == HID_C == OUT_C == 128

#define SCAN_CHUNK 1024
#define SCAN_BLOCKS ((N_NODES + SCAN_CHUNK - 1) / SCAN_CHUNK)   // 98

#define GBM 128
#define PIPE_CHUNKS 4
#define CHUNK_NODES (196 * GBM)   // 25088, GBM-aligned

// ---------------- device scratch (no allocations allowed) ----------------
__device__ __half2 g_h[(size_t)N_NODES * C / 2];  // layer-1 GEMM out (UNSCALED), fp16
__device__ __half2 g_h2[(size_t)N_NODES * C / 2]; // layer-2 GEMM out (UNSCALED), fp16
__device__ float   g_a[(size_t)N_NODES * C];      // layer-1 activation (GEMM2 input)
__device__ int     g_cnt[N_NODES];                // in-degree counts (excl self-loop)
__device__ int     g_cursor[N_NODES];             // absolute fill cursors (init = rowstart)
__device__ int     g_rowstart[N_NODES + 1];       // CSR row offsets
__device__ float   g_inv[N_NODES];                // 1/sqrt(deg) with self-loop
__device__ int     g_esrc[N_EDGES];               // CSR: src node per slot (grouped by dst)
__device__ int     g_part[SCAN_BLOCKS];           // per-chunk partial sums
__device__ int     g_mode64;                      // 1 if edge_index is int64, 0 if int32

// ---------------- probe dtype + zero counts (fused) ----------------
__global__ void probe_zero_kernel(const void* __restrict__ ei) {
    int i = blockIdx.x * blockDim.x + threadIdx.x;
    if (i < N_NODES) g_cnt[i] = 0;
    if (blockIdx.x == 0) {
        __shared__ int bad;
        if (threadIdx.x == 0) bad = 0;
        __syncthreads();
        const long long* p = (const long long*)ei;
        for (int k = threadIdx.x; k < 2048; k += blockDim.x) {
            long long v = p[k];
            if (v < 0 || v >= N_NODES) bad = 1;
        }
        __syncthreads();
        if (threadIdx.x == 0) g_mode64 = bad ? 0 : 1;
    }
}

// ---------------- count: 4 edges per thread ----------------
__global__ void count_kernel(const void* __restrict__ ei) {
    int t = blockIdx.x * blockDim.x + threadIdx.x;        // 0 .. N_EDGES/4-1
    if (t >= N_EDGES / 4) return;
    if (!g_mode64) {
        const int4* dst4 = (const int4*)((const int*)ei + N_EDGES);
        int4 d = dst4[t];
        if ((unsigned)d.x < N_NODES) atomicAdd(&g_cnt[d.x], 1);
        if ((unsigned)d.y < N_NODES) atomicAdd(&g_cnt[d.y], 1);
        if ((unsigned)d.z < N_NODES) atomicAdd(&g_cnt[d.z], 1);
        if ((unsigned)d.w < N_NODES) atomicAdd(&g_cnt[d.w], 1);
    } else {
        const long long* dst = (const long long*)ei + N_EDGES;
        #pragma unroll
        for (int k = 0; k < 4; k++) {
            int d = (int)dst[t * 4 + k];
            if ((unsigned)d < N_NODES) atomicAdd(&g_cnt[d], 1);
        }
    }
}

// ---------------- 3-pass parallel scan ----------------
__global__ __launch_bounds__(256) void scanA_kernel() {
    const int b = blockIdx.x, tid = threadIdx.x;
    int base = b * SCAN_CHUNK + tid * 4;
    int s = 0;
    if (base + 3 < N_NODES) {
        int4 v = *(const int4*)&g_cnt[base];
        s = (v.x + v.y) + (v.z + v.w);
    } else {
        #pragma unroll
        for (int k = 0; k < 4; k++) { int i = base + k; if (i < N_NODES) s += g_cnt[i]; }
    }
    __shared__ int ws[8];
    #pragma unroll
    for (int o = 16; o > 0; o >>= 1) s += __shfl_down_sync(0xFFFFFFFFu, s, o);
    if ((tid & 31) == 0) ws[tid >> 5] = s;
    __syncthreads();
    if (tid < 8) {
        int t = ws[tid];
        #pragma unroll
        for (int o = 4; o > 0; o >>= 1) t += __shfl_down_sync(0xFFu, t, o);
        if (tid == 0) g_part[b] = t;
    }
}

__global__ void scanB_kernel() {
    __shared__ int sh[SCAN_BLOCKS];
    int tid = threadIdx.x;   // 128 threads
    if (tid < SCAN_BLOCKS) sh[tid] = g_part[tid];
    __syncthreads();
    if (tid == 0) {
        int run = 0;
        for (int i = 0; i < SCAN_BLOCKS; i++) { int c = sh[i]; sh[i] = run; run += c; }
        g_rowstart[N_NODES] = run;
    }
    __syncthreads();
    if (tid < SCAN_BLOCKS) g_part[tid] = sh[tid];
}

__global__ __launch_bounds__(256) void scanC_kernel() {
    const int b = blockIdx.x, tid = threadIdx.x;
    const int lane = tid & 31, wid = tid >> 5;
    int base = b * SCAN_CHUNK + tid * 4;
    int v0 = 0, v1 = 0, v2 = 0, v3 = 0;
    if (base + 3 < N_NODES) {
        int4 v = *(const int4*)&g_cnt[base];
        v0 = v.x; v1 = v.y; v2 = v.z; v3 = v.w;
    } else {
        if (base + 0 < N_NODES) v0 = g_cnt[base + 0];
        if (base + 1 < N_NODES) v1 = g_cnt[base + 1];
        if (base + 2 < N_NODES) v2 = g_cnt[base + 2];
        if (base + 3 < N_NODES) v3 = g_cnt[base + 3];
    }
    int s = (v0 + v1) + (v2 + v3);

    int x = s;
    #pragma unroll
    for (int o = 1; o < 32; o <<= 1) {
        int t = __shfl_up_sync(0xFFFFFFFFu, x, o);
        if (lane >= o) x += t;
    }
    __shared__ int wsum[8];
    if (lane == 31) wsum[wid] = x;
    __syncthreads();
    if (tid < 8) {
        int w = wsum[tid];
        #pragma unroll
        for (int o = 1; o < 8; o <<= 1) {
            int t = __shfl_up_sync(0xFFu, w, o);
            if (tid >= o) w += t;
        }
        wsum[tid] = w;
    }
    __syncthreads();
    int ex = (wid ? wsum[wid - 1] : 0) + x - s;
    int off = g_part[b] + ex;

    int p0 = off, p1 = off + v0, p2 = p1 + v1, p3 = p2 + v2;
    if (base + 3 < N_NODES) {
        *(int4*)&g_rowstart[base] = make_int4(p0, p1, p2, p3);
        *(int4*)&g_cursor[base]   = make_int4(p0, p1, p2, p3);
        *(float4*)&g_inv[base] = make_float4(
            rsqrtf((float)v0 + 1.0f), rsqrtf((float)v1 + 1.0f),
            rsqrtf((float)v2 + 1.0f), rsqrtf((float)v3 + 1.0f));
    } else {
        int p[4] = {p0, p1, p2, p3};
        int vv[4] = {v0, v1, v2, v3};
        #pragma unroll
        for (int k = 0; k < 4; k++) {
            int i = base + k;
            if (i < N_NODES) {
                g_rowstart[i] = p[k];
                g_cursor[i] = p[k];
                g_inv[i] = rsqrtf((float)vv[k] + 1.0f);
            }
        }
    }
}

// ---------------- fill: 4 edges per thread, absolute cursors ----------------
__global__ void fill_kernel(const void* __restrict__ ei) {
    int t = blockIdx.x * blockDim.x + threadIdx.x;
    if (t >= N_EDGES / 4) return;
    int d[4], s[4];
    if (!g_mode64) {
        const int4* src4 = (const int4*)((const int*)ei);
        const int4* dst4 = (const int4*)((const int*)ei + N_EDGES);
        int4 dv = dst4[t], sv = src4[t];
        d[0] = dv.x; d[1] = dv.y; d[2] = dv.z; d[3] = dv.w;
        s[0] = sv.x; s[1] = sv.y; s[2] = sv.z; s[3] = sv.w;
    } else {
        const long long* srcp = (const long long*)ei;
        const long long* dstp = srcp + N_EDGES;
        #pragma unroll
        for (int k = 0; k < 4; k++) { s[k] = (int)srcp[t * 4 + k]; d[k] = (int)dstp[t * 4 + k]; }
    }
    #pragma unroll
    for (int k = 0; k < 4; k++) {
        if ((unsigned)d[k] < N_NODES && (unsigned)s[k] < N_NODES) {
            int pos = atomicAdd(&g_cursor[d[k]], 1);
            if ((unsigned)pos < N_EDGES) g_esrc[pos] = s[k];
        }
    }
}

// ---------------- tf32 tensor-core GEMM, UNSCALED fp16 output ----------------
// TO_H2 selects output buffer (false: g_h, true: g_h2) -> no WAR with agg1 gathers.
__device__ __forceinline__ float cvt_tf32(float x) {
    uint32_t u;
    asm("cvt.rna.tf32.f32 %0, %1;" : "=r"(u) : "f"(x));
    return __uint_as_float(u);
}

__device__ __forceinline__ void mma_tf32(float* c, const uint32_t* a, uint32_t b0, uint32_t b1) {
    asm volatile(
        "mma.sync.aligned.m16n8k8.row.col.f32.tf32.tf32.f32 "
        "{%0,%1,%2,%3},{%4,%5,%6,%7},{%8,%9},{%0,%1,%2,%3};"
        : "+f"(c[0]), "+f"(c[1]), "+f"(c[2]), "+f"(c[3])
        : "r"(a[0]), "r"(a[1]), "r"(a[2]), "r"(a[3]), "r"(b0), "r"(b1));
}

template <bool FROM_GA, bool TO_H2>
__global__ __launch_bounds__(256) void gemm_tf32(const float* __restrict__ Aext,
                                                 const float* __restrict__ W,
                                                 int mbase) {
    const float* __restrict__ A = FROM_GA ? g_a : Aext;
    __shared__ float As[GBM][36];   // 128 rows x 32 k (pad -> conflict-free frag loads)
    __shared__ float Bst[C][36];    // transposed W tile: [col][k_local]

    const int tid = threadIdx.x;
    const int lane = tid & 31, wid = tid >> 5;
    const int g = lane >> 2, tig = lane & 3;
    const int rm = (wid & 3) * 32;   // warp row base (4 warps over M)
    const int cn = (wid >> 2) * 64;  // warp col base (2 warps over N)
    const int m0 = mbase + blockIdx.x * GBM;

    float acc[2][8][4] = {};

    for (int kk = 0; kk < C; kk += 32) {
        #pragma unroll
        for (int l = 0; l < 4; l++) {
            int slot = tid + l * 256;          // 0..1023
            int row = slot >> 3, kg = slot & 7;
            int gr = m0 + row;
            float4 v = make_float4(0.f, 0.f, 0.f, 0.f);
            if (gr < N_NODES) v = *(const float4*)&A[(size_t)gr * C + kk + kg * 4];
            *(float4*)&As[row][kg * 4] =
                make_float4(cvt_tf32(v.x), cvt_tf32(v.y), cvt_tf32(v.z), cvt_tf32(v.w));
        }
        #pragma unroll
        for (int l = 0; l < 4; l++) {
            int slot = tid + l * 256;
            int kr = slot & 31, cg = slot >> 5;
            float4 w = *(const float4*)&W[(size_t)(kk + kr) * C + cg * 4];
            Bst[cg * 4 + 0][kr] = cvt_tf32(w.x);
            Bst[cg * 4 + 1][kr] = cvt_tf32(w.y);
            Bst[cg * 4 + 2][kr] = cvt_tf32(w.z);
            Bst[cg * 4 + 3][kr] = cvt_tf32(w.w);
        }
        __syncthreads();

        #pragma unroll
        for (int k4 = 0; k4 < 4; k4++) {
            const int k = k4 * 8;
            uint32_t a[2][4];
            #pragma unroll
            for (int i = 0; i < 2; i++) {
                int r = rm + i * 16 + g;
                a[i][0] = __float_as_uint(As[r][k + tig]);
                a[i][1] = __float_as_uint(As[r + 8][k + tig]);
                a[i][2] = __float_as_uint(As[r][k + tig + 4]);
                a[i][3] = __float_as_uint(As[r + 8][k + tig + 4]);
            }
            #pragma unroll
            for (int j = 0; j < 8; j++) {
                int col = cn + j * 8 + g;
                uint32_t b0 = __float_as_uint(Bst[col][k + tig]);
                uint32_t b1 = __float_as_uint(Bst[col][k + tig + 4]);
                mma_tf32(acc[0][j], a[0], b0, b1);
                mma_tf32(acc[1][j], a[1], b0, b1);
            }
        }
        __syncthreads();
    }

    // epilogue: store raw fp16 (no scaling)
    __half* __restrict__ H = TO_H2 ? (__half*)g_h2 : (__half*)g_h;
    #pragma unroll
    for (int i = 0; i < 2; i++) {
        int r0 = m0 + rm + i * 16 + g;
        int r1 = r0 + 8;
        #pragma unroll
        for (int j = 0; j < 8; j++) {
            int colb = cn + j * 8 + tig * 2;
            if (r0 < N_NODES) {
                uint32_t p;
                asm("cvt.rn.f16x2.f32 %0, %1, %2;" : "=r"(p)
                    : "f"(acc[i][j][1]), "f"(acc[i][j][0]));
                *(uint32_t*)&H[(size_t)r0 * C + colb] = p;
            }
            if (r1 < N_NODES) {
                uint32_t p;
                asm("cvt.rn.f16x2.f32 %0, %1, %2;" : "=r"(p)
                    : "f"(acc[i][j][3]), "f"(acc[i][j][2]));
                *(uint32_t*)&H[(size_t)r1 * C + colb] = p;
            }
        }
    }
}

// ---------------- aggregation: one warp per node, fp16 gather + per-edge weight ----
// out[n] = inv[n]*( sum_e inv[src]*h[src] + inv[n]*h[n] ) + bias
__device__ __forceinline__ void fma_h2x2(uint2 u, float w, float4& acc) {
    asm("{\n\t"
        ".reg .f16 l0, h0, l1, h1;\n\t"
        ".reg .f32 f0, f1, f2, f3;\n\t"
        "mov.b32 {l0, h0}, %4;\n\t"
        "mov.b32 {l1, h1}, %5;\n\t"
        "cvt.f32.f16 f0, l0;\n\t"
        "cvt.f32.f16 f1, h0;\n\t"
        "cvt.f32.f16 f2, l1;\n\t"
        "cvt.f32.f16 f3, h1;\n\t"
        "fma.rn.f32 %0, f0, %6, %0;\n\t"
        "fma.rn.f32 %1, f1, %6, %1;\n\t"
        "fma.rn.f32 %2, f2, %6, %2;\n\t"
        "fma.rn.f32 %3, f3, %6, %3;\n\t"
        "}"
        : "+f"(acc.x), "+f"(acc.y), "+f"(acc.z), "+f"(acc.w)
        : "r"(u.x), "r"(u.y), "f"(w));
}

template <bool TO_GA, bool FROM_H2>
__global__ __launch_bounds__(256) void agg_kernel(const float* __restrict__ bias,
                                                  float* __restrict__ out,
                                                  int nbase, int nend) {
    int gw = (blockIdx.x * blockDim.x + threadIdx.x) >> 5;
    int lane = threadIdx.x & 31;
    const int n = nbase + gw;
    if (n >= nend) return;
    const uint2* __restrict__ hv = FROM_H2 ? (const uint2*)g_h2 : (const uint2*)g_h;

    float4 acc = make_float4(0.f, 0.f, 0.f, 0.f);
    const int e0 = g_rowstart[n];
    const int e1 = g_rowstart[n + 1];
    int e = e0;
    for (; e + 4 <= e1; e += 4) {
        int s0 = g_esrc[e + 0], s1 = g_esrc[e + 1], s2 = g_esrc[e + 2], s3 = g_esrc[e + 3];
        float w0 = g_inv[s0], w1 = g_inv[s1], w2 = g_inv[s2], w3 = g_inv[s3];
        uint2 u0 = hv[(size_t)s0 * 32 + lane];
        uint2 u1 = hv[(size_t)s1 * 32 + lane];
        uint2 u2 = hv[(size_t)s2 * 32 + lane];
        uint2 u3 = hv[(size_t)s3 * 32 + lane];
        fma_h2x2(u0, w0, acc); fma_h2x2(u1, w1, acc);
        fma_h2x2(u2, w2, acc); fma_h2x2(u3, w3, acc);
    }
    for (; e < e1; e++) {
        int s = g_esrc[e];
        fma_h2x2(hv[(size_t)s * 32 + lane], g_inv[s], acc);
    }

    const float invd = g_inv[n];
    fma_h2x2(hv[(size_t)n * 32 + lane], invd, acc);   // self contribution
    float4 bb = ((const float4*)bias)[lane];
    float4 o;
    o.x = invd * acc.x + bb.x;
    o.y = invd * acc.y + bb.y;
    o.z = invd * acc.z + bb.z;
    o.w = invd * acc.w + bb.w;
    if (TO_GA) {
        o.x = fmaxf(o.x, 0.f); o.y = fmaxf(o.y, 0.f);
        o.z = fmaxf(o.z, 0.f); o.w = fmaxf(o.w, 0.f);
        ((float4*)g_a)[(size_t)n * 32 + lane] = o;
    } else {
        ((float4*)out)[(size_t)n * 32 + lane] = o;
    }
}

// ---------------- launch: gemm1 forked at t=0; agg1/gemm2 chunk-pipelined ----------
struct SideCtx {
    cudaStream_t s1 = nullptr;
    cudaEvent_t ev_fork = nullptr, ev_g1 = nullptr, ev_g2 = nullptr;
    cudaEvent_t ev_a[PIPE_CHUNKS] = {};
    bool ok = false;
    SideCtx() {
        ok = (cudaStreamCreateWithFlags(&s1, cudaStreamNonBlocking) == cudaSuccess) &&
             (cudaEventCreateWithFlags(&ev_fork, cudaEventDisableTiming) == cudaSuccess) &&
             (cudaEventCreateWithFlags(&ev_g1, cudaEventDisableTiming) == cudaSuccess) &&
             (cudaEventCreateWithFlags(&ev_g2, cudaEventDisableTiming) == cudaSuccess);
        for (int k = 0; k < PIPE_CHUNKS && ok; k++)
            ok = (cudaEventCreateWithFlags(&ev_a[k], cudaEventDisableTiming) == cudaSuccess);
    }
};

extern "C" void kernel_launch(void* const* d_in, const int* in_sizes, int n_in,
                              void* d_out, int out_size) {
    const float* x  = (const float*)d_in[0];
    const void*  ei = d_in[1];
    const float* W1 = (const float*)d_in[2];
    const float* b1 = (const float*)d_in[3];
    const float* W2 = (const float*)d_in[4];
    const float* b2 = (const float*)d_in[5];
    float* out = (float*)d_out;

    static SideCtx ctx;   // created once on the first (non-capture) call

    const int TB = 256;
    const int nodeBlocks = (N_NODES + TB - 1) / TB;
    const int edge4Blocks = (N_EDGES / 4 + TB - 1) / TB;
    const int gemmBlocksAll = (N_NODES + GBM - 1) / GBM;   // 782
    const int aggBlocksAll = (N_NODES * 32 + TB - 1) / TB;

    if (ctx.ok) {
        // fork gemm1 immediately: depends only on x, W1 -> writes g_h
        cudaEventRecord(ctx.ev_fork, 0);
        cudaStreamWaitEvent(ctx.s1, ctx.ev_fork, 0);
        gemm_tf32<false, false><<<gemmBlocksAll, TB, 0, ctx.s1>>>(x, W1, 0);
        cudaEventRecord(ctx.ev_g1, ctx.s1);

        // main stream: CSR build
        probe_zero_kernel<<<nodeBlocks, TB>>>(ei);
        count_kernel<<<edge4Blocks, TB>>>(ei);
        scanA_kernel<<<SCAN_BLOCKS, 256>>>();
        scanB_kernel<<<1, 128>>>();
        scanC_kernel<<<SCAN_BLOCKS, 256>>>();
        fill_kernel<<<edge4Blocks, TB>>>(ei);
        cudaStreamWaitEvent(0, ctx.ev_g1, 0);   // agg1 needs gemm1 done

        // pipelined: agg1 chunk k (main, g_h -> g_a) -> gemm2 chunk k (side, g_a -> g_h2)
        for (int k = 0; k < PIPE_CHUNKS; k++) {
            int nb = k * CHUNK_NODES;
            int ne = (k == PIPE_CHUNKS - 1) ? N_NODES : nb + CHUNK_NODES;
            int blocks = ((ne - nb) * 32 + TB - 1) / TB;
            agg_kernel<true, false><<<blocks, TB>>>(b1, nullptr, nb, ne);
            cudaEventRecord(ctx.ev_a[k], 0);
            cudaStreamWaitEvent(ctx.s1, ctx.ev_a[k], 0);
            int gblocks = (ne - nb + GBM - 1) / GBM;
            gemm_tf32<true, true><<<gblocks, TB, 0, ctx.s1>>>(nullptr, W2, nb);
        }
        cudaEventRecord(ctx.ev_g2, ctx.s1);
        cudaStreamWaitEvent(0, ctx.ev_g2, 0);   // agg2 needs all of gemm2

        agg_kernel<false, true><<<aggBlocksAll, TB>>>(b2, out, 0, N_NODES);
    } else {
        // serial fallback
        probe_zero_kernel<<<nodeBlocks, TB>>>(ei);
        count_kernel<<<edge4Blocks, TB>>>(ei);
        scanA_kernel<<<SCAN_BLOCKS, 256>>>();
        scanB_kernel<<<1, 128>>>();
        scanC_kernel<<<SCAN_BLOCKS, 256>>>();
        fill_kernel<<<edge4Blocks, TB>>>(ei);
        gemm_tf32<false, false><<<gemmBlocksAll, TB>>>(x, W1, 0);
        agg_kernel<true, false><<<aggBlocksAll, TB>>>(b1, nullptr, 0, N_NODES);
        gemm_tf32<true, true><<<gemmBlocksAll, TB>>>(nullptr, W2, 0);
        agg_kernel<false, true><<<aggBlocksAll, TB>>>(b2, out, 0, N_NODES);
    }
}

// round 16
// speedup vs baseline: 1.0967x; 1.0967x over previous
#include <cuda_runtime.h>
#include <cuda_fp16.h>
#include <cstdint>

#define N_NODES 100000
#define N_EDGES 1600000
#define C 128          // IN_C == HID_C == OUT_C == 128

#define SCAN_CHUNK 1024
#define SCAN_BLOCKS ((N_NODES + SCAN_CHUNK - 1) / SCAN_CHUNK)   // 98

#define GBM 128

// ---------------- device scratch (no allocations allowed) ----------------
__device__ __half2 g_h[(size_t)N_NODES * C / 2]; // GEMM out (UNSCALED), fp16 (both layers)
__device__ uint2   g_af[(size_t)N_NODES * C / 4];// layer-1 activation, fp16 (gemm2 input)
__device__ int     g_cnt[N_NODES];               // in-degree counts (excl self-loop)
__device__ int     g_cursor[N_NODES];            // absolute fill cursors (init = rowstart)
__device__ int     g_rowstart[N_NODES + 1];      // CSR row offsets
__device__ float   g_inv[N_NODES];               // 1/sqrt(deg) with self-loop
__device__ int     g_esrc[N_EDGES];              // CSR: src node per slot (grouped by dst)
__device__ int     g_part[SCAN_BLOCKS];          // per-chunk partial sums
__device__ int     g_mode64;                     // 1 if edge_index is int64, 0 if int32

// ---------------- probe dtype + zero counts (fused) ----------------
__global__ void probe_zero_kernel(const void* __restrict__ ei) {
    int i = blockIdx.x * blockDim.x + threadIdx.x;
    if (i < N_NODES) g_cnt[i] = 0;
    if (blockIdx.x == 0) {
        __shared__ int bad;
        if (threadIdx.x == 0) bad = 0;
        __syncthreads();
        const long long* p = (const long long*)ei;
        for (int k = threadIdx.x; k < 2048; k += blockDim.x) {
            long long v = p[k];
            if (v < 0 || v >= N_NODES) bad = 1;
        }
        __syncthreads();
        if (threadIdx.x == 0) g_mode64 = bad ? 0 : 1;
    }
}

// ---------------- count: 4 edges per thread ----------------
__global__ void count_kernel(const void* __restrict__ ei) {
    int t = blockIdx.x * blockDim.x + threadIdx.x;        // 0 .. N_EDGES/4-1
    if (t >= N_EDGES / 4) return;
    if (!g_mode64) {
        const int4* dst4 = (const int4*)((const int*)ei + N_EDGES);
        int4 d = dst4[t];
        if ((unsigned)d.x < N_NODES) atomicAdd(&g_cnt[d.x], 1);
        if ((unsigned)d.y < N_NODES) atomicAdd(&g_cnt[d.y], 1);
        if ((unsigned)d.z < N_NODES) atomicAdd(&g_cnt[d.z], 1);
        if ((unsigned)d.w < N_NODES) atomicAdd(&g_cnt[d.w], 1);
    } else {
        const long long* dst = (const long long*)ei + N_EDGES;
        #pragma unroll
        for (int k = 0; k < 4; k++) {
            int d = (int)dst[t * 4 + k];
            if ((unsigned)d < N_NODES) atomicAdd(&g_cnt[d], 1);
        }
    }
}

// ---------------- 3-pass parallel scan ----------------
__global__ __launch_bounds__(256) void scanA_kernel() {
    const int b = blockIdx.x, tid = threadIdx.x;
    int base = b * SCAN_CHUNK + tid * 4;
    int s = 0;
    if (base + 3 < N_NODES) {
        int4 v = *(const int4*)&g_cnt[base];
        s = (v.x + v.y) + (v.z + v.w);
    } else {
        #pragma unroll
        for (int k = 0; k < 4; k++) { int i = base + k; if (i < N_NODES) s += g_cnt[i]; }
    }
    __shared__ int ws[8];
    #pragma unroll
    for (int o = 16; o > 0; o >>= 1) s += __shfl_down_sync(0xFFFFFFFFu, s, o);
    if ((tid & 31) == 0) ws[tid >> 5] = s;
    __syncthreads();
    if (tid < 8) {
        int t = ws[tid];
        #pragma unroll
        for (int o = 4; o > 0; o >>= 1) t += __shfl_down_sync(0xFFu, t, o);
        if (tid == 0) g_part[b] = t;
    }
}

__global__ void scanB_kernel() {
    __shared__ int sh[SCAN_BLOCKS];
    int tid = threadIdx.x;   // 128 threads
    if (tid < SCAN_BLOCKS) sh[tid] = g_part[tid];
    __syncthreads();
    if (tid == 0) {
        int run = 0;
        for (int i = 0; i < SCAN_BLOCKS; i++) { int c = sh[i]; sh[i] = run; run += c; }
        g_rowstart[N_NODES] = run;
    }
    __syncthreads();
    if (tid < SCAN_BLOCKS) g_part[tid] = sh[tid];
}

__global__ __launch_bounds__(256) void scanC_kernel() {
    const int b = blockIdx.x, tid = threadIdx.x;
    const int lane = tid & 31, wid = tid >> 5;
    int base = b * SCAN_CHUNK + tid * 4;
    int v0 = 0, v1 = 0, v2 = 0, v3 = 0;
    if (base + 3 < N_NODES) {
        int4 v = *(const int4*)&g_cnt[base];
        v0 = v.x; v1 = v.y; v2 = v.z; v3 = v.w;
    } else {
        if (base + 0 < N_NODES) v0 = g_cnt[base + 0];
        if (base + 1 < N_NODES) v1 = g_cnt[base + 1];
        if (base + 2 < N_NODES) v2 = g_cnt[base + 2];
        if (base + 3 < N_NODES) v3 = g_cnt[base + 3];
    }
    int s = (v0 + v1) + (v2 + v3);

    int x = s;
    #pragma unroll
    for (int o = 1; o < 32; o <<= 1) {
        int t = __shfl_up_sync(0xFFFFFFFFu, x, o);
        if (lane >= o) x += t;
    }
    __shared__ int wsum[8];
    if (lane == 31) wsum[wid] = x;
    __syncthreads();
    if (tid < 8) {
        int w = wsum[tid];
        #pragma unroll
        for (int o = 1; o < 8; o <<= 1) {
            int t = __shfl_up_sync(0xFFu, w, o);
            if (tid >= o) w += t;
        }
        wsum[tid] = w;
    }
    __syncthreads();
    int ex = (wid ? wsum[wid - 1] : 0) + x - s;
    int off = g_part[b] + ex;

    int p0 = off, p1 = off + v0, p2 = p1 + v1, p3 = p2 + v2;
    if (base + 3 < N_NODES) {
        *(int4*)&g_rowstart[base] = make_int4(p0, p1, p2, p3);
        *(int4*)&g_cursor[base]   = make_int4(p0, p1, p2, p3);
        *(float4*)&g_inv[base] = make_float4(
            rsqrtf((float)v0 + 1.0f), rsqrtf((float)v1 + 1.0f),
            rsqrtf((float)v2 + 1.0f), rsqrtf((float)v3 + 1.0f));
    } else {
        int p[4] = {p0, p1, p2, p3};
        int vv[4] = {v0, v1, v2, v3};
        #pragma unroll
        for (int k = 0; k < 4; k++) {
            int i = base + k;
            if (i < N_NODES) {
                g_rowstart[i] = p[k];
                g_cursor[i] = p[k];
                g_inv[i] = rsqrtf((float)vv[k] + 1.0f);
            }
        }
    }
}

// ---------------- fill: 4 edges per thread, absolute cursors ----------------
__global__ void fill_kernel(const void* __restrict__ ei) {
    int t = blockIdx.x * blockDim.x + threadIdx.x;
    if (t >= N_EDGES / 4) return;
    int d[4], s[4];
    if (!g_mode64) {
        const int4* src4 = (const int4*)((const int*)ei);
        const int4* dst4 = (const int4*)((const int*)ei + N_EDGES);
        int4 dv = dst4[t], sv = src4[t];
        d[0] = dv.x; d[1] = dv.y; d[2] = dv.z; d[3] = dv.w;
        s[0] = sv.x; s[1] = sv.y; s[2] = sv.z; s[3] = sv.w;
    } else {
        const long long* srcp = (const long long*)ei;
        const long long* dstp = srcp + N_EDGES;
        #pragma unroll
        for (int k = 0; k < 4; k++) { s[k] = (int)srcp[t * 4 + k]; d[k] = (int)dstp[t * 4 + k]; }
    }
    #pragma unroll
    for (int k = 0; k < 4; k++) {
        if ((unsigned)d[k] < N_NODES && (unsigned)s[k] < N_NODES) {
            int pos = atomicAdd(&g_cursor[d[k]], 1);
            if ((unsigned)pos < N_EDGES) g_esrc[pos] = s[k];
        }
    }
}

// ---------------- fp16 m16n8k16 tensor-core GEMM, UNSCALED fp16 output ----------
// fp16 mantissa (10 bits) == tf32 mantissa -> same precision as before, 2x rate.
__device__ __forceinline__ void mma_f16(float* c, const uint32_t* a, uint32_t b0, uint32_t b1) {
    asm volatile(
        "mma.sync.aligned.m16n8k16.row.col.f32.f16.f16.f32 "
        "{%0,%1,%2,%3},{%4,%5,%6,%7},{%8,%9},{%0,%1,%2,%3};"
        : "+f"(c[0]), "+f"(c[1]), "+f"(c[2]), "+f"(c[3])
        : "r"(a[0]), "r"(a[1]), "r"(a[2]), "r"(a[3]), "r"(b0), "r"(b1));
}

__device__ __forceinline__ uint32_t pack_h2(float lo, float hi) {
    uint32_t p;
    asm("cvt.rn.f16x2.f32 %0, %1, %2;" : "=r"(p) : "f"(hi), "f"(lo));
    return p;
}

template <bool FROM_GA>
__global__ __launch_bounds__(256) void gemm_f16(const float* __restrict__ Aext,
                                                const float* __restrict__ W) {
    __shared__ __half As[GBM][40];   // 128 rows x 32 k fp16 (pad 40 -> conflict-free frags)
    __shared__ __half Bs[C][40];     // transposed W tile: [col][k_local] fp16

    const int tid = threadIdx.x;
    const int lane = tid & 31, wid = tid >> 5;
    const int g = lane >> 2, tig = lane & 3;
    const int rm = (wid & 3) * 32;   // warp row base (4 warps over M)
    const int cn = (wid >> 2) * 64;  // warp col base (2 warps over N)
    const int m0 = blockIdx.x * GBM;

    float acc[2][8][4] = {};

    for (int kk = 0; kk < C; kk += 32) {
        // A tile fill: 4 halves (8B) per slot
        #pragma unroll
        for (int l = 0; l < 4; l++) {
            int slot = tid + l * 256;          // 0..1023
            int row = slot >> 3, kg = slot & 7;
            int gr = m0 + row;
            uint32_t p0 = 0, p1 = 0;
            if (gr < N_NODES) {
                if (FROM_GA) {
                    uint2 v = g_af[(size_t)gr * 32 + (kk >> 2) + kg];
                    p0 = v.x; p1 = v.y;
                } else {
                    float4 v = *(const float4*)&Aext[(size_t)gr * C + kk + kg * 4];
                    p0 = pack_h2(v.x, v.y);
                    p1 = pack_h2(v.z, v.w);
                }
            }
            *(uint32_t*)&As[row][kg * 4] = p0;
            *(uint32_t*)&As[row][kg * 4 + 2] = p1;
        }
        // W tile fill: transposed [col][k]
        #pragma unroll
        for (int l = 0; l < 4; l++) {
            int slot = tid + l * 256;
            int kr = slot & 31, cg = slot >> 5;
            float4 w = *(const float4*)&W[(size_t)(kk + kr) * C + cg * 4];
            Bs[cg * 4 + 0][kr] = __float2half(w.x);
            Bs[cg * 4 + 1][kr] = __float2half(w.y);
            Bs[cg * 4 + 2][kr] = __float2half(w.z);
            Bs[cg * 4 + 3][kr] = __float2half(w.w);
        }
        __syncthreads();

        // 2 k-steps of 16 per tile
        #pragma unroll
        for (int ks = 0; ks < 2; ks++) {
            const int k0 = ks * 16;
            uint32_t a[2][4];
            #pragma unroll
            for (int i = 0; i < 2; i++) {
                int r = rm + i * 16 + g;
                a[i][0] = *(const uint32_t*)&As[r][k0 + 2 * tig];
                a[i][1] = *(const uint32_t*)&As[r + 8][k0 + 2 * tig];
                a[i][2] = *(const uint32_t*)&As[r][k0 + 2 * tig + 8];
                a[i][3] = *(const uint32_t*)&As[r + 8][k0 + 2 * tig + 8];
            }
            #pragma unroll
            for (int j = 0; j < 8; j++) {
                int col = cn + j * 8 + g;
                uint32_t b0 = *(const uint32_t*)&Bs[col][k0 + 2 * tig];
                uint32_t b1 = *(const uint32_t*)&Bs[col][k0 + 2 * tig + 8];
                mma_f16(acc[0][j], a[0], b0, b1);
                mma_f16(acc[1][j], a[1], b0, b1);
            }
        }
        __syncthreads();
    }

    // epilogue: store raw fp16 (no scaling) to g_h
    __half* __restrict__ H = (__half*)g_h;
    #pragma unroll
    for (int i = 0; i < 2; i++) {
        int r0 = m0 + rm + i * 16 + g;
        int r1 = r0 + 8;
        #pragma unroll
        for (int j = 0; j < 8; j++) {
            int colb = cn + j * 8 + tig * 2;
            if (r0 < N_NODES)
                *(uint32_t*)&H[(size_t)r0 * C + colb] = pack_h2(acc[i][j][0], acc[i][j][1]);
            if (r1 < N_NODES)
                *(uint32_t*)&H[(size_t)r1 * C + colb] = pack_h2(acc[i][j][2], acc[i][j][3]);
        }
    }
}

// ---------------- aggregation: one warp per node, fp16 gather + per-edge weight ----
// out[n] = inv[n]*( sum_e inv[src]*h[src] + inv[n]*h[n] ) + bias
__device__ __forceinline__ void fma_h2x2(uint2 u, float w, float4& acc) {
    asm("{\n\t"
        ".reg .f16 l0, h0, l1, h1;\n\t"
        ".reg .f32 f0, f1, f2, f3;\n\t"
        "mov.b32 {l0, h0}, %4;\n\t"
        "mov.b32 {l1, h1}, %5;\n\t"
        "cvt.f32.f16 f0, l0;\n\t"
        "cvt.f32.f16 f1, h0;\n\t"
        "cvt.f32.f16 f2, l1;\n\t"
        "cvt.f32.f16 f3, h1;\n\t"
        "fma.rn.f32 %0, f0, %6, %0;\n\t"
        "fma.rn.f32 %1, f1, %6, %1;\n\t"
        "fma.rn.f32 %2, f2, %6, %2;\n\t"
        "fma.rn.f32 %3, f3, %6, %3;\n\t"
        "}"
        : "+f"(acc.x), "+f"(acc.y), "+f"(acc.z), "+f"(acc.w)
        : "r"(u.x), "r"(u.y), "f"(w));
}

template <bool TO_GA>
__global__ __launch_bounds__(256) void agg_kernel(const float* __restrict__ bias,
                                                  float* __restrict__ out) {
    int gw = (blockIdx.x * blockDim.x + threadIdx.x) >> 5;
    int lane = threadIdx.x & 31;
    if (gw >= N_NODES) return;
    const int n = gw;
    const uint2* __restrict__ hv = (const uint2*)g_h;   // 32 uint2 per 256B row

    float4 acc = make_float4(0.f, 0.f, 0.f, 0.f);
    const int e0 = g_rowstart[n];
    const int e1 = g_rowstart[n + 1];
    int e = e0;
    for (; e + 4 <= e1; e += 4) {
        int s0 = g_esrc[e + 0], s1 = g_esrc[e + 1], s2 = g_esrc[e + 2], s3 = g_esrc[e + 3];
        float w0 = g_inv[s0], w1 = g_inv[s1], w2 = g_inv[s2], w3 = g_inv[s3];
        uint2 u0 = hv[(size_t)s0 * 32 + lane];
        uint2 u1 = hv[(size_t)s1 * 32 + lane];
        uint2 u2 = hv[(size_t)s2 * 32 + lane];
        uint2 u3 = hv[(size_t)s3 * 32 + lane];
        fma_h2x2(u0, w0, acc); fma_h2x2(u1, w1, acc);
        fma_h2x2(u2, w2, acc); fma_h2x2(u3, w3, acc);
    }
    for (; e < e1; e++) {
        int s = g_esrc[e];
        fma_h2x2(hv[(size_t)s * 32 + lane], g_inv[s], acc);
    }

    const float invd = g_inv[n];
    fma_h2x2(hv[(size_t)n * 32 + lane], invd, acc);   // self contribution
    float4 bb = ((const float4*)bias)[lane];
    float4 o;
    o.x = invd * acc.x + bb.x;
    o.y = invd * acc.y + bb.y;
    o.z = invd * acc.z + bb.z;
    o.w = invd * acc.w + bb.w;
    if (TO_GA) {
        o.x = fmaxf(o.x, 0.f); o.y = fmaxf(o.y, 0.f);
        o.z = fmaxf(o.z, 0.f); o.w = fmaxf(o.w, 0.f);
        uint32_t p0, p1;
        asm("cvt.rn.f16x2.f32 %0, %1, %2;" : "=r"(p0) : "f"(o.y), "f"(o.x));
        asm("cvt.rn.f16x2.f32 %0, %1, %2;" : "=r"(p1) : "f"(o.w), "f"(o.z));
        g_af[(size_t)n * 32 + lane] = make_uint2(p0, p1);
    } else {
        ((float4*)out)[(size_t)n * 32 + lane] = o;
    }
}

// ---------------- launch: gemm1 forked at t=0 over the CSR build; serial tail ------
struct SideCtx {
    cudaStream_t s1 = nullptr;
    cudaEvent_t ev_fork = nullptr, ev_g1 = nullptr;
    bool ok = false;
    SideCtx() {
        ok = (cudaStreamCreateWithFlags(&s1, cudaStreamNonBlocking) == cudaSuccess) &&
             (cudaEventCreateWithFlags(&ev_fork, cudaEventDisableTiming) == cudaSuccess) &&
             (cudaEventCreateWithFlags(&ev_g1, cudaEventDisableTiming) == cudaSuccess);
    }
};

extern "C" void kernel_launch(void* const* d_in, const int* in_sizes, int n_in,
                              void* d_out, int out_size) {
    const float* x  = (const float*)d_in[0];
    const void*  ei = d_in[1];
    const float* W1 = (const float*)d_in[2];
    const float* b1 = (const float*)d_in[3];
    const float* W2 = (const float*)d_in[4];
    const float* b2 = (const float*)d_in[5];
    float* out = (float*)d_out;

    static SideCtx ctx;   // created once on the first (non-capture) call

    const int TB = 256;
    const int nodeBlocks = (N_NODES + TB - 1) / TB;
    const int edge4Blocks = (N_EDGES / 4 + TB - 1) / TB;
    const int gemmBlocks = (N_NODES + GBM - 1) / GBM;
    const int aggBlocks = (N_NODES * 32 + TB - 1) / TB;

    if (ctx.ok) {
        // fork gemm1 immediately: depends only on x, W1 -> writes g_h
        cudaEventRecord(ctx.ev_fork, 0);
        cudaStreamWaitEvent(ctx.s1, ctx.ev_fork, 0);
        gemm_f16<false><<<gemmBlocks, TB, 0, ctx.s1>>>(x, W1);
        cudaEventRecord(ctx.ev_g1, ctx.s1);

        // main stream: full CSR build (hides gemm1)
        probe_zero_kernel<<<nodeBlocks, TB>>>(ei);
        count_kernel<<<edge4Blocks, TB>>>(ei);
        scanA_kernel<<<SCAN_BLOCKS, 256>>>();
        scanB_kernel<<<1, 128>>>();
        scanC_kernel<<<SCAN_BLOCKS, 256>>>();
        fill_kernel<<<edge4Blocks, TB>>>(ei);

        cudaStreamWaitEvent(0, ctx.ev_g1, 0);
    } else {
        probe_zero_kernel<<<nodeBlocks, TB>>>(ei);
        count_kernel<<<edge4Blocks, TB>>>(ei);
        scanA_kernel<<<SCAN_BLOCKS, 256>>>();
        scanB_kernel<<<1, 128>>>();
        scanC_kernel<<<SCAN_BLOCKS, 256>>>();
        fill_kernel<<<edge4Blocks, TB>>>(ei);
        gemm_f16<false><<<gemmBlocks, TB>>>(x, W1);
    }

    // serial tail (L2-friendly: one big consumer at a time)
    agg_kernel<true><<<aggBlocks, TB>>>(b1, nullptr);          // g_h -> g_af (fp16, relu)
    gemm_f16<true><<<gemmBlocks, TB>>>(nullptr, W2);           // g_af -> g_h
    agg_kernel<false><<<aggBlocks, TB>>>(b2, out);             // g_h -> out
}